// round 4
// baseline (speedup 1.0000x reference)
#include <cuda_runtime.h>

#define B_TOT   8192
#define T_IN    1024
#define FUT     64
#define T_OUT   (T_IN + FUT)       // 1088
#define EPB     32                 // elements per block
#define THREADS (EPB * 4)          // 4 threads per element
#define CHUNK   32                 // time steps per x/y staging chunk
#define NCHUNK  (T_OUT / CHUNK)    // 34
#define XSTRIDE 36                 // smem row stride in floats (144 B, 16B-multiple)

__device__ __forceinline__ float sigmoidf_(float x) {
    float e = __expf(-x);
    return __fdividef(1.0f, 1.0f + e);
}
__device__ __forceinline__ float tanhf_(float x) {
    float a = fabsf(x);
    float e = __expf(-2.0f * a);
    float t = __fdividef(1.0f - e, 1.0f + e);
    return copysignf(t, x);
}

// acc += dot(w[0:12], h[0:12]) with vectorized LDS.128 weight reads
__device__ __forceinline__ float dot12(const float* __restrict__ w, const float* h, float acc) {
    const float4* w4 = (const float4*)w;
    float4 a = w4[0], b = w4[1], c = w4[2];
    acc = fmaf(a.x, h[0], acc);  acc = fmaf(a.y, h[1], acc);
    acc = fmaf(a.z, h[2], acc);  acc = fmaf(a.w, h[3], acc);
    acc = fmaf(b.x, h[4], acc);  acc = fmaf(b.y, h[5], acc);
    acc = fmaf(b.z, h[6], acc);  acc = fmaf(b.w, h[7], acc);
    acc = fmaf(c.x, h[8], acc);  acc = fmaf(c.y, h[9], acc);
    acc = fmaf(c.z, h[10], acc); acc = fmaf(c.w, h[11], acc);
    return acc;
}

__global__ __launch_bounds__(THREADS)
void lstm_seq_kernel(const float* __restrict__ input,
                     const float* __restrict__ w_ih1, const float* __restrict__ w_hh1,
                     const float* __restrict__ b_ih1, const float* __restrict__ b_hh1,
                     const float* __restrict__ w_ih2, const float* __restrict__ w_hh2,
                     const float* __restrict__ b_ih2, const float* __restrict__ b_hh2,
                     const float* __restrict__ w_lin, const float* __restrict__ b_lin,
                     float* __restrict__ out)
{
    // alignas(16): every array here is touched by float4 (LDS.128/STS.128);
    // CUDA only guarantees element-type alignment for __shared__ arrays.
    __shared__ alignas(16) float s_wih1[48], s_b1[48], s_b2[48];
    __shared__ alignas(16) float s_whh1[48 * 12], s_wih2[48 * 12], s_whh2[48 * 12];
    __shared__ alignas(16) float s_wlin[12];
    __shared__ float s_blin;
    __shared__ alignas(16) float xbuf[EPB * XSTRIDE];
    __shared__ alignas(16) float ybuf[EPB * XSTRIDE];

    const int tid = threadIdx.x;

    // cooperative weight load (biases pre-summed)
    for (int i = tid; i < 48; i += THREADS) {
        s_wih1[i] = w_ih1[i];
        s_b1[i]   = b_ih1[i] + b_hh1[i];
        s_b2[i]   = b_ih2[i] + b_hh2[i];
    }
    for (int i = tid; i < 48 * 12; i += THREADS) {
        s_whh1[i] = w_hh1[i];
        s_wih2[i] = w_ih2[i];
        s_whh2[i] = w_hh2[i];
    }
    if (tid < 12) s_wlin[tid] = w_lin[tid];
    if (tid == 0) s_blin = b_lin[0];

    const int le  = tid >> 2;   // local element 0..31
    const int sub = tid & 3;    // unit-group 0..3 (owns hidden units u0..u0+2)
    const int u0  = sub * 3;

    // per-thread recurrent state (h replicated, c private to owned units)
    float h1[12], h2[12], c1[3], c2[3];
    #pragma unroll
    for (int j = 0; j < 12; j++) { h1[j] = 0.0f; h2[j] = 0.0f; }
    #pragma unroll
    for (int m = 0; m < 3; m++) { c1[m] = 0.0f; c2[m] = 0.0f; }

    const float* inrow  = input + (size_t)(blockIdx.x * EPB + le) * T_IN;
    float*       outrow = out   + (size_t)(blockIdx.x * EPB + le) * T_OUT;

    for (int c = 0; c < NCHUNK; c++) {
        const int tbase = c * CHUNK;
        // ---- stage x chunk into smem (coalesced float4) ----
        {
            float4 v0, v1;
            if (tbase < T_IN) {
                const float4* p = (const float4*)(inrow + tbase + sub * 8);
                v0 = p[0]; v1 = p[1];
            } else {
                float xl = inrow[T_IN - 1];          // free-running: repeat last input
                v0 = make_float4(xl, xl, xl, xl); v1 = v0;
            }
            float* xb = &xbuf[le * XSTRIDE + sub * 8];
            *(float4*)(xb)     = v0;
            *(float4*)(xb + 4) = v1;
        }
        __syncthreads();   // xbuf ready; also guards prev-chunk ybuf readers

        const float* xrow = &xbuf[le * XSTRIDE];
        #pragma unroll 1
        for (int i = 0; i < CHUNK; i++) {
            const float x = xrow[i];

            // ---------- layer 1 ----------
            float h1n[3];
            #pragma unroll
            for (int m = 0; m < 3; m++) {
                const int u = u0 + m;
                float gi = fmaf(x, s_wih1[u],      s_b1[u]);
                float gf = fmaf(x, s_wih1[12 + u], s_b1[12 + u]);
                float gg = fmaf(x, s_wih1[24 + u], s_b1[24 + u]);
                float go = fmaf(x, s_wih1[36 + u], s_b1[36 + u]);
                gi = dot12(&s_whh1[u * 12],        h1, gi);
                gf = dot12(&s_whh1[(12 + u) * 12], h1, gf);
                gg = dot12(&s_whh1[(24 + u) * 12], h1, gg);
                go = dot12(&s_whh1[(36 + u) * 12], h1, go);
                float cc = sigmoidf_(gf) * c1[m] + sigmoidf_(gi) * tanhf_(gg);
                c1[m] = cc;
                h1n[m] = sigmoidf_(go) * tanhf_(cc);
            }
            // all-gather new h1 across the quad
            #pragma unroll
            for (int s = 0; s < 4; s++) {
                h1[s * 3 + 0] = __shfl_sync(0xffffffffu, h1n[0], s, 4);
                h1[s * 3 + 1] = __shfl_sync(0xffffffffu, h1n[1], s, 4);
                h1[s * 3 + 2] = __shfl_sync(0xffffffffu, h1n[2], s, 4);
            }

            // ---------- layer 2 ----------
            float h2n[3];
            #pragma unroll
            for (int m = 0; m < 3; m++) {
                const int u = u0 + m;
                float gi = s_b2[u];
                float gf = s_b2[12 + u];
                float gg = s_b2[24 + u];
                float go = s_b2[36 + u];
                gi = dot12(&s_wih2[u * 12],        h1, gi);
                gf = dot12(&s_wih2[(12 + u) * 12], h1, gf);
                gg = dot12(&s_wih2[(24 + u) * 12], h1, gg);
                go = dot12(&s_wih2[(36 + u) * 12], h1, go);
                gi = dot12(&s_whh2[u * 12],        h2, gi);
                gf = dot12(&s_whh2[(12 + u) * 12], h2, gf);
                gg = dot12(&s_whh2[(24 + u) * 12], h2, gg);
                go = dot12(&s_whh2[(36 + u) * 12], h2, go);
                float cc = sigmoidf_(gf) * c2[m] + sigmoidf_(gi) * tanhf_(gg);
                c2[m] = cc;
                h2n[m] = sigmoidf_(go) * tanhf_(cc);
            }
            // all-gather new h2 across the quad
            #pragma unroll
            for (int s = 0; s < 4; s++) {
                h2[s * 3 + 0] = __shfl_sync(0xffffffffu, h2n[0], s, 4);
                h2[s * 3 + 1] = __shfl_sync(0xffffffffu, h2n[1], s, 4);
                h2[s * 3 + 2] = __shfl_sync(0xffffffffu, h2n[2], s, 4);
            }

            // ---------- linear head + quad reduce ----------
            float yp = h2n[0] * s_wlin[u0]
                     + h2n[1] * s_wlin[u0 + 1]
                     + h2n[2] * s_wlin[u0 + 2];
            yp += __shfl_xor_sync(0xffffffffu, yp, 1, 4);
            yp += __shfl_xor_sync(0xffffffffu, yp, 2, 4);
            if (sub == 0) ybuf[le * XSTRIDE + i] = yp + s_blin;
        }
        __syncthreads();   // ybuf ready

        // ---- drain y chunk to gmem (coalesced float4) ----
        {
            const float* yb = &ybuf[le * XSTRIDE + sub * 8];
            float4 a = *(const float4*)yb;
            float4 b = *(const float4*)(yb + 4);
            float4* p = (float4*)(outrow + tbase + sub * 8);
            p[0] = a; p[1] = b;
        }
    }
}

extern "C" void kernel_launch(void* const* d_in, const int* in_sizes, int n_in,
                              void* d_out, int out_size) {
    // metadata order: input, future(int scalar), w_ih1, w_hh1, b_ih1, b_hh1,
    //                 w_ih2, w_hh2, b_ih2, b_hh2, w_lin, b_lin
    int base = (n_in >= 12 && in_sizes[1] == 1) ? 2 : 1;  // skip 'future' scalar if present
    const float* input = (const float*)d_in[0];
    const float* w_ih1 = (const float*)d_in[base + 0];
    const float* w_hh1 = (const float*)d_in[base + 1];
    const float* b_ih1 = (const float*)d_in[base + 2];
    const float* b_hh1 = (const float*)d_in[base + 3];
    const float* w_ih2 = (const float*)d_in[base + 4];
    const float* w_hh2 = (const float*)d_in[base + 5];
    const float* b_ih2 = (const float*)d_in[base + 6];
    const float* b_hh2 = (const float*)d_in[base + 7];
    const float* w_lin = (const float*)d_in[base + 8];
    const float* b_lin = (const float*)d_in[base + 9];

    lstm_seq_kernel<<<B_TOT / EPB, THREADS>>>(
        input, w_ih1, w_hh1, b_ih1, b_hh1,
        w_ih2, w_hh2, b_ih2, b_hh2, w_lin, b_lin,
        (float*)d_out);
}

// round 5
// speedup vs baseline: 1.0614x; 1.0614x over previous
#include <cuda_runtime.h>

#define B_TOT   8192
#define T_IN    1024
#define FUT     64
#define T_OUT   (T_IN + FUT)       // 1088
#define EPB     32                 // elements per block
#define THREADS (EPB * 4)          // 4 threads per element
#define CHUNK   32                 // time steps per x/y staging chunk
#define NCHUNK  (T_OUT / CHUNK)    // 34
#define XSTRIDE 36                 // smem row stride in floats (144 B, 16B-multiple)

// 1-MUFU tanh (sm_75+). max abs err ~1e-5: fine for 1e-3 gate through a
// contractive recurrence.
__device__ __forceinline__ float tanh_fast(float x) {
    float y;
    asm("tanh.approx.f32 %0, %1;" : "=f"(y) : "f"(x));
    return y;
}
// sigmoid(x) = 0.5*tanh(x/2) + 0.5  -> 1 MUFU + 2 FMA
__device__ __forceinline__ float sigf(float x) {
    return fmaf(tanh_fast(0.5f * x), 0.5f, 0.5f);
}

// acc += dot(w[0:12], h[0:12]) with vectorized LDS.128 weight reads
__device__ __forceinline__ float dot12(const float* __restrict__ w, const float* h, float acc) {
    const float4* w4 = (const float4*)w;
    float4 a = w4[0], b = w4[1], c = w4[2];
    acc = fmaf(a.x, h[0], acc);  acc = fmaf(a.y, h[1], acc);
    acc = fmaf(a.z, h[2], acc);  acc = fmaf(a.w, h[3], acc);
    acc = fmaf(b.x, h[4], acc);  acc = fmaf(b.y, h[5], acc);
    acc = fmaf(b.z, h[6], acc);  acc = fmaf(b.w, h[7], acc);
    acc = fmaf(c.x, h[8], acc);  acc = fmaf(c.y, h[9], acc);
    acc = fmaf(c.z, h[10], acc); acc = fmaf(c.w, h[11], acc);
    return acc;
}

__global__ __launch_bounds__(THREADS)
void lstm_seq_kernel(const float* __restrict__ input,
                     const float* __restrict__ w_ih1, const float* __restrict__ w_hh1,
                     const float* __restrict__ b_ih1, const float* __restrict__ b_hh1,
                     const float* __restrict__ w_ih2, const float* __restrict__ w_hh2,
                     const float* __restrict__ b_ih2, const float* __restrict__ b_hh2,
                     const float* __restrict__ w_lin, const float* __restrict__ b_lin,
                     float* __restrict__ out)
{
    // alignas(16): touched by float4 (LDS.128/STS.128)
    __shared__ alignas(16) float s_whh1[48 * 12], s_wih2[48 * 12], s_whh2[48 * 12];
    __shared__ alignas(16) float xbuf[EPB * XSTRIDE];
    __shared__ alignas(16) float ybuf[EPB * XSTRIDE];

    const int tid = threadIdx.x;

    for (int i = tid; i < 48 * 12; i += THREADS) {
        s_whh1[i] = w_hh1[i];
        s_wih2[i] = w_ih2[i];
        s_whh2[i] = w_hh2[i];
    }

    const int le  = tid >> 2;   // local element 0..31
    const int sub = tid & 3;    // unit-group 0..3 (owns hidden units u0..u0+2)
    const int u0  = sub * 3;

    // per-thread constants in registers (read once from gmem, L1/L2 served)
    float wi1[12], bb1[12], bb2[12], wl[3];
    #pragma unroll
    for (int g = 0; g < 4; g++) {
        #pragma unroll
        for (int m = 0; m < 3; m++) {
            const int r = g * 12 + u0 + m;
            wi1[g * 3 + m] = w_ih1[r];
            bb1[g * 3 + m] = b_ih1[r] + b_hh1[r];
            bb2[g * 3 + m] = b_ih2[r] + b_hh2[r];
        }
    }
    #pragma unroll
    for (int m = 0; m < 3; m++) wl[m] = w_lin[u0 + m];
    const float blin = b_lin[0];

    // per-thread recurrent state (h replicated, c private to owned units)
    float h1[12], h2[12], c1[3], c2[3];
    #pragma unroll
    for (int j = 0; j < 12; j++) { h1[j] = 0.0f; h2[j] = 0.0f; }
    #pragma unroll
    for (int m = 0; m < 3; m++) { c1[m] = 0.0f; c2[m] = 0.0f; }

    const float* inrow  = input + (size_t)(blockIdx.x * EPB + le) * T_IN;
    float*       outrow = out   + (size_t)(blockIdx.x * EPB + le) * T_OUT;

    __syncthreads();   // weights staged

    for (int c = 0; c < NCHUNK; c++) {
        const int tbase = c * CHUNK;
        // ---- stage x chunk into smem (coalesced float4) ----
        {
            float4 v0, v1;
            if (tbase < T_IN) {
                const float4* p = (const float4*)(inrow + tbase + sub * 8);
                v0 = p[0]; v1 = p[1];
            } else {
                float xl = inrow[T_IN - 1];          // free-running: repeat last input
                v0 = make_float4(xl, xl, xl, xl); v1 = v0;
            }
            float* xb = &xbuf[le * XSTRIDE + sub * 8];
            *(float4*)(xb)     = v0;
            *(float4*)(xb + 4) = v1;
        }
        __syncthreads();   // xbuf ready; also guards prev-chunk ybuf readers

        const float* xrow = &xbuf[le * XSTRIDE];
        #pragma unroll 1
        for (int i = 0; i < CHUNK; i++) {
            const float x = xrow[i];

            // ---------- layer 1 ----------
            float h1n[3];
            #pragma unroll
            for (int m = 0; m < 3; m++) {
                const int u = u0 + m;
                float gi = fmaf(x, wi1[m],     bb1[m]);
                float gf = fmaf(x, wi1[3 + m], bb1[3 + m]);
                float gg = fmaf(x, wi1[6 + m], bb1[6 + m]);
                float go = fmaf(x, wi1[9 + m], bb1[9 + m]);
                gi = dot12(&s_whh1[u * 12],        h1, gi);
                gf = dot12(&s_whh1[(12 + u) * 12], h1, gf);
                gg = dot12(&s_whh1[(24 + u) * 12], h1, gg);
                go = dot12(&s_whh1[(36 + u) * 12], h1, go);
                float cc = fmaf(sigf(gf), c1[m], sigf(gi) * tanh_fast(gg));
                c1[m] = cc;
                h1n[m] = sigf(go) * tanh_fast(cc);
            }
            // all-gather new h1 across the quad
            #pragma unroll
            for (int s = 0; s < 4; s++) {
                h1[s * 3 + 0] = __shfl_sync(0xffffffffu, h1n[0], s, 4);
                h1[s * 3 + 1] = __shfl_sync(0xffffffffu, h1n[1], s, 4);
                h1[s * 3 + 2] = __shfl_sync(0xffffffffu, h1n[2], s, 4);
            }

            // ---------- layer 2 ----------
            float h2n[3];
            #pragma unroll
            for (int m = 0; m < 3; m++) {
                const int u = u0 + m;
                float gi = bb2[m];
                float gf = bb2[3 + m];
                float gg = bb2[6 + m];
                float go = bb2[9 + m];
                gi = dot12(&s_wih2[u * 12],        h1, gi);
                gf = dot12(&s_wih2[(12 + u) * 12], h1, gf);
                gg = dot12(&s_wih2[(24 + u) * 12], h1, gg);
                go = dot12(&s_wih2[(36 + u) * 12], h1, go);
                gi = dot12(&s_whh2[u * 12],        h2, gi);
                gf = dot12(&s_whh2[(12 + u) * 12], h2, gf);
                gg = dot12(&s_whh2[(24 + u) * 12], h2, gg);
                go = dot12(&s_whh2[(36 + u) * 12], h2, go);
                float cc = fmaf(sigf(gf), c2[m], sigf(gi) * tanh_fast(gg));
                c2[m] = cc;
                h2n[m] = sigf(go) * tanh_fast(cc);
            }
            // all-gather new h2 across the quad
            #pragma unroll
            for (int s = 0; s < 4; s++) {
                h2[s * 3 + 0] = __shfl_sync(0xffffffffu, h2n[0], s, 4);
                h2[s * 3 + 1] = __shfl_sync(0xffffffffu, h2n[1], s, 4);
                h2[s * 3 + 2] = __shfl_sync(0xffffffffu, h2n[2], s, 4);
            }

            // ---------- linear head + quad reduce ----------
            float yp = h2n[0] * wl[0] + h2n[1] * wl[1] + h2n[2] * wl[2];
            yp += __shfl_xor_sync(0xffffffffu, yp, 1, 4);
            yp += __shfl_xor_sync(0xffffffffu, yp, 2, 4);
            if (sub == 0) ybuf[le * XSTRIDE + i] = yp + blin;
        }
        __syncthreads();   // ybuf ready

        // ---- drain y chunk to gmem (coalesced float4) ----
        {
            const float* yb = &ybuf[le * XSTRIDE + sub * 8];
            float4 a = *(const float4*)yb;
            float4 b = *(const float4*)(yb + 4);
            float4* p = (float4*)(outrow + tbase + sub * 8);
            p[0] = a; p[1] = b;
        }
    }
}

extern "C" void kernel_launch(void* const* d_in, const int* in_sizes, int n_in,
                              void* d_out, int out_size) {
    // metadata order: input, future(int scalar), w_ih1, w_hh1, b_ih1, b_hh1,
    //                 w_ih2, w_hh2, b_ih2, b_hh2, w_lin, b_lin
    int base = (n_in >= 12 && in_sizes[1] == 1) ? 2 : 1;  // skip 'future' scalar if present
    const float* input = (const float*)d_in[0];
    const float* w_ih1 = (const float*)d_in[base + 0];
    const float* w_hh1 = (const float*)d_in[base + 1];
    const float* b_ih1 = (const float*)d_in[base + 2];
    const float* b_hh1 = (const float*)d_in[base + 3];
    const float* w_ih2 = (const float*)d_in[base + 4];
    const float* w_hh2 = (const float*)d_in[base + 5];
    const float* b_ih2 = (const float*)d_in[base + 6];
    const float* b_hh2 = (const float*)d_in[base + 7];
    const float* w_lin = (const float*)d_in[base + 8];
    const float* b_lin = (const float*)d_in[base + 9];

    lstm_seq_kernel<<<B_TOT / EPB, THREADS>>>(
        input, w_ih1, w_hh1, b_ih1, b_hh1,
        w_ih2, w_hh2, b_ih2, b_hh2, w_lin, b_lin,
        (float*)d_out);
}

// round 6
// speedup vs baseline: 1.2945x; 1.2197x over previous
#include <cuda_runtime.h>

#define B_TOT   8192
#define T_IN    1024
#define FUT     64
#define T_OUT   (T_IN + FUT)       // 1088
#define EPB     32                 // elements per block (= lanes per warp)
#define THREADS 128                // 4 warps: warp w owns hidden units 3w..3w+2
#define CHUNK   32
#define NCHUNK  (T_OUT / CHUNK)    // 34
#define XST     36                 // x/y smem stride (float4-aligned rows)
#define HST     13                 // h-exchange stride (odd -> conflict-free)

typedef unsigned long long ull;

// ---- f32x2 packed helpers (Blackwell packed fp32; rounding == scalar FFMA) ----
__device__ __forceinline__ ull pk2(float lo, float hi) {
    ull r;
    asm("mov.b64 %0, {%1, %2};" : "=l"(r) : "f"(lo), "f"(hi));
    return r;
}
__device__ __forceinline__ ull ffma2(ull a, ull b, ull c) {
    ull d;
    asm("fma.rn.f32x2 %0, %1, %2, %3;" : "=l"(d) : "l"(a), "l"(b), "l"(c));
    return d;
}
__device__ __forceinline__ float2 unpk(ull v) {
    float lo, hi;
    asm("mov.b64 {%0, %1}, %2;" : "=f"(lo), "=f"(hi) : "l"(v));
    return make_float2(lo, hi);
}

// 1-MUFU tanh; sigmoid via tanh identity (2 extra fma-pipe ops)
__device__ __forceinline__ float tanh_fast(float x) {
    float y;
    asm("tanh.approx.f32 %0, %1;" : "=f"(y) : "f"(x));
    return y;
}
__device__ __forceinline__ float sigf(float x) {
    return fmaf(tanh_fast(0.5f * x), 0.5f, 0.5f);
}

// acc += sum_j hh[j] * w2[j]  over a packed pair-row (12 float2 = 6 LDS.128,
// warp-uniform address -> broadcast, 1 wavefront each)
__device__ __forceinline__ ull dotpk(const float2* __restrict__ row, const ull* hh, ull acc) {
    const ulonglong2* p = (const ulonglong2*)row;
    #pragma unroll
    for (int jj = 0; jj < 6; jj++) {
        ulonglong2 v = p[jj];
        acc = ffma2(hh[2 * jj],     v.x, acc);
        acc = ffma2(hh[2 * jj + 1], v.y, acc);
    }
    return acc;
}

__global__ __launch_bounds__(THREADS)
void lstm_seq_kernel(const float* __restrict__ input,
                     const float* __restrict__ w_ih1, const float* __restrict__ w_hh1,
                     const float* __restrict__ b_ih1, const float* __restrict__ b_hh1,
                     const float* __restrict__ w_ih2, const float* __restrict__ w_hh2,
                     const float* __restrict__ b_ih2, const float* __restrict__ b_hh2,
                     const float* __restrict__ w_lin, const float* __restrict__ b_lin,
                     float* __restrict__ out)
{
    // packed weights: per unit u, pair-row 0 = (i,f) gates, 1 = (g,o) gates;
    // entry [ (u*2+pair)*12 + j ] = (W[gA*12+u][j], W[gB*12+u][j])
    __shared__ alignas(16) float2 s_pk1[288];   // w_hh1 packed
    __shared__ alignas(16) float2 s_pki2[288];  // w_ih2 packed
    __shared__ alignas(16) float2 s_pkh2[288];  // w_hh2 packed
    __shared__ alignas(16) float xbuf[EPB * XST];
    __shared__ alignas(16) float ybuf[EPB * XST];
    __shared__ float h1buf[EPB * HST];
    __shared__ float h2buf[EPB * HST];

    const int tid  = threadIdx.x;
    const int sub  = tid >> 5;     // warp id = unit group
    const int lane = tid & 31;     // element within block
    const int u0   = sub * 3;

    // build packed weight layout
    for (int idx = tid; idx < 288; idx += THREADS) {
        int u = idx / 24, rem = idx % 24, pair = rem / 12, j = rem % 12;
        int rA = (pair ? 24 : 0) + u;
        int rB = (pair ? 36 : 12) + u;
        s_pk1[idx]  = make_float2(w_hh1[rA * 12 + j], w_hh1[rB * 12 + j]);
        s_pki2[idx] = make_float2(w_ih2[rA * 12 + j], w_ih2[rB * 12 + j]);
        s_pkh2[idx] = make_float2(w_hh2[rA * 12 + j], w_hh2[rB * 12 + j]);
    }

    // warp-uniform packed constants (x-weights + pre-summed biases)
    ull wx_if[3], wx_go[3], bz1_if[3], bz1_go[3], bz2_if[3], bz2_go[3];
    #pragma unroll
    for (int m = 0; m < 3; m++) {
        const int u = u0 + m;
        wx_if[m]  = pk2(w_ih1[u],        w_ih1[12 + u]);
        wx_go[m]  = pk2(w_ih1[24 + u],   w_ih1[36 + u]);
        bz1_if[m] = pk2(b_ih1[u] + b_hh1[u],           b_ih1[12 + u] + b_hh1[12 + u]);
        bz1_go[m] = pk2(b_ih1[24 + u] + b_hh1[24 + u], b_ih1[36 + u] + b_hh1[36 + u]);
        bz2_if[m] = pk2(b_ih2[u] + b_hh2[u],           b_ih2[12 + u] + b_hh2[12 + u]);
        bz2_go[m] = pk2(b_ih2[24 + u] + b_hh2[24 + u], b_ih2[36 + u] + b_hh2[36 + u]);
    }
    float wl[12];
    #pragma unroll
    for (int j = 0; j < 12; j++) wl[j] = w_lin[j];
    const float blin = b_lin[0];

    // recurrent state: h replicated as (h,h) packs, c private to owned units
    ull hh1[12], hh2[12];
    float c1[3], c2[3];
    #pragma unroll
    for (int j = 0; j < 12; j++) { hh1[j] = 0ULL; hh2[j] = 0ULL; }
    #pragma unroll
    for (int m = 0; m < 3; m++) { c1[m] = 0.0f; c2[m] = 0.0f; }

    const float* inrow  = input + (size_t)(blockIdx.x * EPB + lane) * T_IN;
    float*       outrow = out   + (size_t)(blockIdx.x * EPB + lane) * T_OUT;

    __syncthreads();   // packed weights staged

    for (int c = 0; c < NCHUNK; c++) {
        const int tbase = c * CHUNK;
        // ---- stage x chunk (each warp loads 8 of the 32 步 floats per element) ----
        {
            float4 v0, v1;
            if (tbase < T_IN) {
                const float4* p = (const float4*)(inrow + tbase + sub * 8);
                v0 = p[0]; v1 = p[1];
            } else {
                float xl = inrow[T_IN - 1];   // free-running: repeat last input
                v0 = make_float4(xl, xl, xl, xl); v1 = v0;
            }
            float* xb = &xbuf[lane * XST + sub * 8];
            *(float4*)(xb)     = v0;
            *(float4*)(xb + 4) = v1;
        }
        __syncthreads();

        #pragma unroll 1
        for (int i = 0; i < CHUNK; i++) {
            const float x = xbuf[lane * XST + i];
            const ull xx = pk2(x, x);

            // ---------- layer 1 (units u0..u0+2) ----------
            float h1n[3];
            #pragma unroll
            for (int m = 0; m < 3; m++) {
                const int u = u0 + m;
                ull aif = ffma2(xx, wx_if[m], bz1_if[m]);
                ull ago = ffma2(xx, wx_go[m], bz1_go[m]);
                aif = dotpk(&s_pk1[u * 24],      hh1, aif);
                ago = dotpk(&s_pk1[u * 24 + 12], hh1, ago);
                float2 gif = unpk(aif);
                float2 ggo = unpk(ago);
                float si = sigf(gif.x), sf = sigf(gif.y);
                float tg = tanh_fast(ggo.x), so = sigf(ggo.y);
                float cc = fmaf(sf, c1[m], si * tg);
                c1[m] = cc;
                h1n[m] = so * tanh_fast(cc);
            }
            h1buf[lane * HST + u0 + 0] = h1n[0];
            h1buf[lane * HST + u0 + 1] = h1n[1];
            h1buf[lane * HST + u0 + 2] = h1n[2];
            __syncthreads();
            #pragma unroll
            for (int j = 0; j < 12; j++) {
                float v = h1buf[lane * HST + j];
                hh1[j] = pk2(v, v);
            }

            // ---------- layer 2 ----------
            float h2n[3];
            #pragma unroll
            for (int m = 0; m < 3; m++) {
                const int u = u0 + m;
                ull aif = bz2_if[m];
                ull ago = bz2_go[m];
                aif = dotpk(&s_pki2[u * 24],      hh1, aif);
                ago = dotpk(&s_pki2[u * 24 + 12], hh1, ago);
                aif = dotpk(&s_pkh2[u * 24],      hh2, aif);
                ago = dotpk(&s_pkh2[u * 24 + 12], hh2, ago);
                float2 gif = unpk(aif);
                float2 ggo = unpk(ago);
                float si = sigf(gif.x), sf = sigf(gif.y);
                float tg = tanh_fast(ggo.x), so = sigf(ggo.y);
                float cc = fmaf(sf, c2[m], si * tg);
                c2[m] = cc;
                h2n[m] = so * tanh_fast(cc);
            }
            h2buf[lane * HST + u0 + 0] = h2n[0];
            h2buf[lane * HST + u0 + 1] = h2n[1];
            h2buf[lane * HST + u0 + 2] = h2n[2];
            __syncthreads();
            float y = blin;
            #pragma unroll
            for (int j = 0; j < 12; j++) {
                float v = h2buf[lane * HST + j];
                hh2[j] = pk2(v, v);
                y = fmaf(v, wl[j], y);
            }
            if (sub == 0) ybuf[lane * XST + i] = y;   // ordered by next bar / final bar
        }
        __syncthreads();   // last y write visible to all warps

        // ---- drain y chunk to gmem ----
        {
            const float* yb = &ybuf[lane * XST + sub * 8];
            float4 a = *(const float4*)yb;
            float4 b = *(const float4*)(yb + 4);
            float4* p = (float4*)(outrow + tbase + sub * 8);
            p[0] = a; p[1] = b;
        }
    }
}

extern "C" void kernel_launch(void* const* d_in, const int* in_sizes, int n_in,
                              void* d_out, int out_size) {
    // metadata order: input, future(int scalar), w_ih1, w_hh1, b_ih1, b_hh1,
    //                 w_ih2, w_hh2, b_ih2, b_hh2, w_lin, b_lin
    int base = (n_in >= 12 && in_sizes[1] == 1) ? 2 : 1;  // skip 'future' scalar if present
    const float* input = (const float*)d_in[0];
    const float* w_ih1 = (const float*)d_in[base + 0];
    const float* w_hh1 = (const float*)d_in[base + 1];
    const float* b_ih1 = (const float*)d_in[base + 2];
    const float* b_hh1 = (const float*)d_in[base + 3];
    const float* w_ih2 = (const float*)d_in[base + 4];
    const float* w_hh2 = (const float*)d_in[base + 5];
    const float* b_ih2 = (const float*)d_in[base + 6];
    const float* b_hh2 = (const float*)d_in[base + 7];
    const float* w_lin = (const float*)d_in[base + 8];
    const float* b_lin = (const float*)d_in[base + 9];

    lstm_seq_kernel<<<B_TOT / EPB, THREADS>>>(
        input, w_ih1, w_hh1, b_ih1, b_hh1,
        w_ih2, w_hh2, b_ih2, b_hh2, w_lin, b_lin,
        (float*)d_out);
}